// round 7
// baseline (speedup 1.0000x reference)
#include <cuda_runtime.h>

// Fixed shapes
#define HH   512
#define WW   512
#define HWSZ (HH * WW)          // 262144 = 2^18
#define BB   4
#define CC   21
#define NPIX (BB * HWSZ)        // 1048576
#define TILE 32                 // 32x32 tiles
#define TPP  (TILE * TILE)      // 1024
#define NTILES (BB * 16 * 16)   // 1024 blocks
#define FBLOCKS 4096            // k_final blocks (1 px/thread)
#define MAXMERGE 65536          // >= total boundary edges (61440)

// Static device scratch
__device__ int           g_labels[NPIX];
__device__ int           g_counts[NPIX];   // final size at every local root
__device__ unsigned char g_tgt[NPIX];
__device__ float         g_partial[FBLOCKS];
__device__ int           g_merged[MAXMERGE];
__device__ int           g_nm;
__device__ unsigned      g_cnt_boundary;

// ---------------------------------------------------------------------------
// Shared-memory union-find (tile-local)
// ---------------------------------------------------------------------------
__device__ __forceinline__ int sfind(volatile int* lab, int x) {
    int y = lab[x];
    while (y != x) { x = y; y = lab[x]; }
    return x;
}
__device__ __forceinline__ void sunite(int* lab, int a, int b) {
    while (true) {
        a = sfind(lab, a);
        b = sfind(lab, b);
        if (a == b) return;
        int mx = a > b ? a : b;
        int mn = a > b ? b : a;
        int old = atomicMin(&lab[mx], mn);
        if (old == mx) return;
        a = old; b = mn;
    }
}
// Global union-find with volatile reads (same-kernel visibility of atomicMin
// results living in L2; avoids stale L1 hits).
__device__ __forceinline__ int gfindv(int x) {
    int y = *(volatile int*)&g_labels[x];
    while (y != x) { x = y; y = *(volatile int*)&g_labels[x]; }
    return x;
}
// Records each root exactly once when it ceases to be a root.
__device__ __forceinline__ void gunite(int a, int b) {
    while (true) {
        a = gfindv(a);
        b = gfindv(b);
        if (a == b) return;
        int mx = a > b ? a : b;
        int mn = a > b ? b : a;
        int old = atomicMin(&g_labels[mx], mn);
        if (old == mx) {
            int s = atomicAdd(&g_nm, 1);
            g_merged[s] = mx;
            return;
        }
        a = old; b = mn;
    }
}

// ---------------------------------------------------------------------------
// k_local: fused dtype-detect + normalize + tile-local CCL + size histogram.
// 32x32 tile, 256 threads (4 px/thread), 1024 blocks.
// ---------------------------------------------------------------------------
__global__ void __launch_bounds__(256) k_local(const void* __restrict__ t) {
    __shared__ unsigned char st[TPP];
    __shared__ int           sl[TPP];
    __shared__ int           scount[TPP];

    // Per-block dtype self-detection on the first 512 32-bit words (in range
    // for both dtypes). int64 targets 0..20 -> odd words all zero; int32 ->
    // each odd word nonzero w.p. 20/21 => P(misdetect) ~ 21^-256.
    unsigned hw = ((const unsigned*)t)[2 * threadIdx.x + 1];
    int is32 = __syncthreads_or(hw != 0u);

    if (blockIdx.x == 0 && threadIdx.x == 0) {
        g_nm = 0; g_cnt_boundary = 0;
    }

    int tile = blockIdx.x;
    int img  = tile >> 8;                 // 256 tiles per image
    int ty   = (tile >> 4) & 15;
    int tx   = tile & 15;
    int base = img * HWSZ + (ty * TILE) * WW + tx * TILE;

#pragma unroll
    for (int k = 0; k < 4; k++) {
        int i  = threadIdx.x + k * 256;
        int gp = base + (i >> 5) * WW + (i & 31);
        int v  = is32 ? ((const int*)t)[gp]
                      : (int)((const long long*)t)[gp];
        st[i] = (unsigned char)v;
        sl[i] = i;
        scount[i] = 0;
        g_tgt[gp] = (unsigned char)v;
    }
    __syncthreads();

#pragma unroll
    for (int k = 0; k < 4; k++) {
        int i = threadIdx.x + k * 256;
        int c = st[i];
        if (c) {
            if ((i & 31) != 31 && st[i + 1]  == c) sunite(sl, i, i + 1);
            if (i < TPP - TILE && st[i + 32] == c) sunite(sl, i, i + 32);
        }
    }
    __syncthreads();

    // compress, write global labels, histogram fg pixels onto local roots
#pragma unroll
    for (int k = 0; k < 4; k++) {
        int i  = threadIdx.x + k * 256;
        int r  = sfind(sl, i);
        int gp = base + (i >> 5) * WW + (i & 31);
        g_labels[gp] = base + (r >> 5) * WW + (r & 31);
        if (st[i]) atomicAdd(&scount[r], 1);
    }
    __syncthreads();

    // roots export their local component size
#pragma unroll
    for (int k = 0; k < 4; k++) {
        int i = threadIdx.x + k * 256;
        if (sl[i] == i) {
            int gp = base + (i >> 5) * WW + (i & 31);
            g_counts[gp] = scount[i];
        }
    }
}

// ---------------------------------------------------------------------------
// k_boundary: cross-tile merges (15 v-seams + 15 h-seams per image, 512
// edges each -> 61440 edges, 240 blocks). The last block runs a two-phase
// fixup that leaves the FINAL component size at EVERY local root, so k_final
// never has to chase the merge chain.
// ---------------------------------------------------------------------------
#define EDGES_PER_DIR (15 * 512)
#define EDGES_PER_IMG (2 * EDGES_PER_DIR)
#define NEDGES (BB * EDGES_PER_IMG)        // 61440
#define BBLOCKS (NEDGES / 256)             // 240

__global__ void __launch_bounds__(256) k_boundary() {
    int e = blockIdx.x * 256 + threadIdx.x;
    int img = e / EDGES_PER_IMG;
    int rem = e % EDGES_PER_IMG;
    int dir = rem / EDGES_PER_DIR;
    int k   = rem % EDGES_PER_DIR;
    int b   = k >> 9;
    int t   = k & 511;

    int p, q;
    if (dir == 0) {            // vertical seam between tile cols b, b+1
        int x = b * TILE + (TILE - 1);
        p = img * HWSZ + t * WW + x;
        q = p + 1;
    } else {                   // horizontal seam between tile rows b, b+1
        int y = b * TILE + (TILE - 1);
        p = img * HWSZ + y * WW + t;
        q = p + WW;
    }
    int c = g_tgt[p];
    if (c && g_tgt[q] == c) gunite(g_labels[p], g_labels[q]);

    // sound last-block protocol: publish writes, then race for last slot
    __threadfence();
    __syncthreads();
    __shared__ int isLast;
    if (threadIdx.x == 0) {
        unsigned r = atomicAdd(&g_cnt_boundary, 1u);
        isLast = (r == BBLOCKS - 1);
    }
    __syncthreads();

    if (isLast) {
        int nm = g_nm;
        // phase 1: accumulate merged local sizes onto final roots
        for (int i = threadIdx.x; i < nm; i += 256) {
            int r = g_merged[i];
            int f = gfindv(r);
            atomicAdd(&g_counts[f], *(volatile int*)&g_counts[r]);
        }
        __threadfence();
        __syncthreads();
        // phase 2: broadcast final size back to each merged local root
        for (int i = threadIdx.x; i < nm; i += 256) {
            int r = g_merged[i];
            int f = gfindv(r);
            *(volatile int*)&g_counts[r] = *(volatile int*)&g_counts[f];
        }
    }
}

// ---------------------------------------------------------------------------
// k_final: fused CE + weight + block reduction, 1 pixel/thread. Weight needs
// only counts[labels[p]] (no chase): every local root already holds the
// final component size.
// ---------------------------------------------------------------------------
__global__ void __launch_bounds__(256) k_final(const float* __restrict__ logits) {
    __shared__ float sh[256];
    const float inv_log501 = 0.16085946f;   // 1/ln(501)

    int p   = blockIdx.x * 256 + threadIdx.x;
    int b   = p >> 18;
    int pix = p & (HWSZ - 1);
    const float* base = logits + ((size_t)b * CC) * HWSZ + pix;

    int ti = g_tgt[p];
    float v[CC];
    float m = -1e30f, tv = 0.f;
#pragma unroll
    for (int c = 0; c < CC; c++) {
        v[c] = base[(size_t)c * HWSZ];
        m = fmaxf(m, v[c]);
        if (c == ti) tv = v[c];
    }
    float s = 0.f;
#pragma unroll
    for (int c = 0; c < CC; c++) s += __expf(v[c] - m);

    float ce = m + __logf(s) - tv;

    float wgt = 1.f;
    if (ti > 0) {
        int sz = g_counts[g_labels[p]];
        if (sz < 500)
            wgt = 3.f * __logf((float)sz + 1.f) * inv_log501;
    }

    sh[threadIdx.x] = ce * wgt;
    __syncthreads();
#pragma unroll
    for (int s2 = 128; s2 > 0; s2 >>= 1) {
        if (threadIdx.x < s2) sh[threadIdx.x] += sh[threadIdx.x + s2];
        __syncthreads();
    }
    if (threadIdx.x == 0) g_partial[blockIdx.x] = sh[0];
}

// Deterministic final reduction
__global__ void k_reduce(float* __restrict__ out) {
    __shared__ float sh[256];
    float a = 0.f;
    for (int i = threadIdx.x; i < FBLOCKS; i += 256) a += g_partial[i];
    sh[threadIdx.x] = a;
    __syncthreads();
#pragma unroll
    for (int s = 128; s > 0; s >>= 1) {
        if (threadIdx.x < s) sh[threadIdx.x] += sh[threadIdx.x + s];
        __syncthreads();
    }
    if (threadIdx.x == 0) out[0] = sh[0] * (1.f / (float)NPIX);
}

// ---------------------------------------------------------------------------
extern "C" void kernel_launch(void* const* d_in, const int* in_sizes, int n_in,
                              void* d_out, int out_size) {
    const float* logits = (const float*)d_in[0];
    const void*  tgt    = d_in[1];
    float*       out    = (float*)d_out;

    k_local   <<<NTILES, 256>>>(tgt);
    k_boundary<<<BBLOCKS, 256>>>();
    k_final   <<<FBLOCKS, 256>>>(logits);
    k_reduce  <<<1, 256>>>(out);
}

// round 8
// speedup vs baseline: 1.5337x; 1.5337x over previous
#include <cuda_runtime.h>

// Fixed shapes
#define HH   512
#define WW   512
#define HWSZ (HH * WW)          // 262144 = 2^18
#define BB   4
#define CC   21
#define NPIX (BB * HWSZ)        // 1048576
#define TILE 32                 // 32x32 tiles
#define TPP  (TILE * TILE)      // 1024
#define NTILES (BB * 16 * 16)   // 1024 blocks
#define FBLOCKS 4096            // k_final blocks (1 px/thread)
#define MAXMERGE 65536          // >= total boundary edges (61440)

// Static device scratch
__device__ int           g_labels[NPIX];
__device__ int           g_counts[NPIX];   // component size at local roots
__device__ unsigned char g_tgt[NPIX];
__device__ float         g_partial[FBLOCKS];
__device__ int           g_merged[MAXMERGE];
__device__ int           g_nm;

// ---------------------------------------------------------------------------
// Shared-memory union-find (tile-local)
// ---------------------------------------------------------------------------
__device__ __forceinline__ int sfind(volatile int* lab, int x) {
    int y = lab[x];
    while (y != x) { x = y; y = lab[x]; }
    return x;
}
__device__ __forceinline__ void sunite(int* lab, int a, int b) {
    while (true) {
        a = sfind(lab, a);
        b = sfind(lab, b);
        if (a == b) return;
        int mx = a > b ? a : b;
        int mn = a > b ? b : a;
        int old = atomicMin(&lab[mx], mn);
        if (old == mx) return;
        a = old; b = mn;
    }
}
// Global union-find (plain loads: labels decrease monotonically, atomicMin is
// the authoritative op, so stale reads only cause a retry -- R2-proven).
__device__ __forceinline__ int gfind(int x) {
    int y = g_labels[x];
    while (y != x) { x = y; y = g_labels[x]; }
    return x;
}
// Records each root exactly once, at the moment it ceases to be a root.
__device__ __forceinline__ void gunite(int a, int b) {
    while (true) {
        a = gfind(a);
        b = gfind(b);
        if (a == b) return;
        int mx = a > b ? a : b;
        int mn = a > b ? b : a;
        int old = atomicMin(&g_labels[mx], mn);
        if (old == mx) {
            int s = atomicAdd(&g_nm, 1);
            g_merged[s] = mx;
            return;
        }
        a = old; b = mn;
    }
}

// ---------------------------------------------------------------------------
// k_local: fused dtype-detect + normalize + tile-local CCL + size histogram.
// 32x32 tile, 256 threads (4 px/thread), 1024 blocks.
// ---------------------------------------------------------------------------
__global__ void __launch_bounds__(256) k_local(const void* __restrict__ t) {
    __shared__ unsigned char st[TPP];
    __shared__ int           sl[TPP];
    __shared__ int           scount[TPP];

    // Per-block dtype self-detection on the first 512 32-bit words (in range
    // for both dtypes). int64 targets 0..20 -> odd words all zero; int32 ->
    // each odd word nonzero w.p. 20/21 => P(misdetect) ~ 21^-256.
    unsigned hw = ((const unsigned*)t)[2 * threadIdx.x + 1];
    int is32 = __syncthreads_or(hw != 0u);

    if (blockIdx.x == 0 && threadIdx.x == 0) g_nm = 0;

    int tile = blockIdx.x;
    int img  = tile >> 8;                 // 256 tiles per image
    int ty   = (tile >> 4) & 15;
    int tx   = tile & 15;
    int base = img * HWSZ + (ty * TILE) * WW + tx * TILE;

#pragma unroll
    for (int k = 0; k < 4; k++) {
        int i  = threadIdx.x + k * 256;
        int gp = base + (i >> 5) * WW + (i & 31);
        int v  = is32 ? ((const int*)t)[gp]
                      : (int)((const long long*)t)[gp];
        st[i] = (unsigned char)v;
        sl[i] = i;
        scount[i] = 0;
        g_tgt[gp] = (unsigned char)v;
    }
    __syncthreads();

#pragma unroll
    for (int k = 0; k < 4; k++) {
        int i = threadIdx.x + k * 256;
        int c = st[i];
        if (c) {
            if ((i & 31) != 31 && st[i + 1]  == c) sunite(sl, i, i + 1);
            if (i < TPP - TILE && st[i + 32] == c) sunite(sl, i, i + 32);
        }
    }
    __syncthreads();

    // compress, write global labels, histogram fg pixels onto local roots
#pragma unroll
    for (int k = 0; k < 4; k++) {
        int i  = threadIdx.x + k * 256;
        int r  = sfind(sl, i);
        int gp = base + (i >> 5) * WW + (i & 31);
        g_labels[gp] = base + (r >> 5) * WW + (r & 31);
        if (st[i]) atomicAdd(&scount[r], 1);
    }
    __syncthreads();

    // roots export their local component size
#pragma unroll
    for (int k = 0; k < 4; k++) {
        int i = threadIdx.x + k * 256;
        if (sl[i] == i) {
            int gp = base + (i >> 5) * WW + (i & 31);
            g_counts[gp] = scount[i];
        }
    }
}

// ---------------------------------------------------------------------------
// k_boundary: cross-tile merges. 15 v-seams + 15 h-seams per image, 512
// edges each -> 61440 edges, 240 blocks. No tails.
// ---------------------------------------------------------------------------
#define EDGES_PER_DIR (15 * 512)
#define EDGES_PER_IMG (2 * EDGES_PER_DIR)
#define NEDGES (BB * EDGES_PER_IMG)        // 61440
#define BBLOCKS (NEDGES / 256)             // 240

__global__ void __launch_bounds__(256) k_boundary() {
    int e = blockIdx.x * 256 + threadIdx.x;
    int img = e / EDGES_PER_IMG;
    int rem = e % EDGES_PER_IMG;
    int dir = rem / EDGES_PER_DIR;
    int k   = rem % EDGES_PER_DIR;
    int b   = k >> 9;
    int t   = k & 511;

    int p, q;
    if (dir == 0) {            // vertical seam between tile cols b, b+1
        int x = b * TILE + (TILE - 1);
        p = img * HWSZ + t * WW + x;
        q = p + 1;
    } else {                   // horizontal seam between tile rows b, b+1
        int y = b * TILE + (TILE - 1);
        p = img * HWSZ + y * WW + t;
        q = p + WW;
    }
    int c = g_tgt[p];
    if (c && g_tgt[q] == c) gunite(g_labels[p], g_labels[q]);
}

// ---------------------------------------------------------------------------
// k_fixup: single block, two phases split by __syncthreads.
//  phase 1: each merged local root adds its size onto its final root
//  phase 2: each merged local root copies back the final size
// After this, EVERY local root holds the final component size, so k_final
// needs no chain chase. ~2.8K merged roots expected.
// ---------------------------------------------------------------------------
__global__ void __launch_bounds__(1024) k_fixup() {
    int nm = g_nm;
    for (int i = threadIdx.x; i < nm; i += 1024) {
        int r = g_merged[i];
        int f = gfind(r);
        atomicAdd(&g_counts[f], *(volatile int*)&g_counts[r]);
    }
    __syncthreads();
    for (int i = threadIdx.x; i < nm; i += 1024) {
        int r = g_merged[i];
        int f = gfind(r);
        *(volatile int*)&g_counts[r] = *(volatile int*)&g_counts[f];
    }
}

// ---------------------------------------------------------------------------
// k_final: fused CE + weight + block reduction, 1 pixel/thread; weight is
// counts[labels[p]] -- identical memory pattern to the 47.6us R2 kernel.
// ---------------------------------------------------------------------------
__global__ void __launch_bounds__(256) k_final(const float* __restrict__ logits) {
    __shared__ float sh[256];
    const float inv_log501 = 0.16085946f;   // 1/ln(501)

    int p   = blockIdx.x * 256 + threadIdx.x;
    int b   = p >> 18;
    int pix = p & (HWSZ - 1);
    const float* base = logits + ((size_t)b * CC) * HWSZ + pix;

    int ti = g_tgt[p];
    float v[CC];
    float m = -1e30f, tv = 0.f;
#pragma unroll
    for (int c = 0; c < CC; c++) {
        v[c] = base[(size_t)c * HWSZ];
        m = fmaxf(m, v[c]);
        if (c == ti) tv = v[c];
    }
    float s = 0.f;
#pragma unroll
    for (int c = 0; c < CC; c++) s += __expf(v[c] - m);

    float ce = m + __logf(s) - tv;

    float wgt = 1.f;
    if (ti > 0) {
        int sz = g_counts[g_labels[p]];
        if (sz < 500)
            wgt = 3.f * __logf((float)sz + 1.f) * inv_log501;
    }

    sh[threadIdx.x] = ce * wgt;
    __syncthreads();
#pragma unroll
    for (int s2 = 128; s2 > 0; s2 >>= 1) {
        if (threadIdx.x < s2) sh[threadIdx.x] += sh[threadIdx.x + s2];
        __syncthreads();
    }
    if (threadIdx.x == 0) g_partial[blockIdx.x] = sh[0];
}

// Deterministic final reduction (single wide block)
__global__ void __launch_bounds__(1024) k_reduce(float* __restrict__ out) {
    __shared__ float sh[1024];
    float a = 0.f;
    for (int i = threadIdx.x; i < FBLOCKS; i += 1024) a += g_partial[i];
    sh[threadIdx.x] = a;
    __syncthreads();
#pragma unroll
    for (int s = 512; s > 0; s >>= 1) {
        if (threadIdx.x < s) sh[threadIdx.x] += sh[threadIdx.x + s];
        __syncthreads();
    }
    if (threadIdx.x == 0) out[0] = sh[0] * (1.f / (float)NPIX);
}

// ---------------------------------------------------------------------------
extern "C" void kernel_launch(void* const* d_in, const int* in_sizes, int n_in,
                              void* d_out, int out_size) {
    const float* logits = (const float*)d_in[0];
    const void*  tgt    = d_in[1];
    float*       out    = (float*)d_out;

    k_local   <<<NTILES, 256>>>(tgt);
    k_boundary<<<BBLOCKS, 256>>>();
    k_fixup   <<<1, 1024>>>();
    k_final   <<<FBLOCKS, 256>>>(logits);
    k_reduce  <<<1, 1024>>>(out);
}